// round 2
// baseline (speedup 1.0000x reference)
#include <cuda_runtime.h>

// Problem constants
#define KC  8192          // number of codes
#define DD  256           // embedding / channel dim
#define NR  16384         // B*H*W rows
#define HW  1024          // H*W
#define CHW (DD * HW)     // per-batch stride in z / out

// Scratch (static device memory — no allocation at runtime)
__device__ float g_codebook[KC * DD];   // emb @ proj_w^T, row-major [K][D]
__device__ int   g_minidx[NR];          // argmin index per row
__device__ float g_partials[512];       // per-block squared-error partial sums

// ---------------------------------------------------------------------------
// Kernel 1: codebook[k][d] = sum_j emb[k][j] * pw[d][j]
// In-order j=0..255, single fp32 accumulator per element -> same rounding
// chain as cuBLAS SGEMM (ascending-k FFMA chain).
// ---------------------------------------------------------------------------
__global__ void codebook_gemm(const float* __restrict__ emb,
                              const float* __restrict__ pw) {
    __shared__ float As[16 * 65];  // [j][k_local]
    __shared__ float Bs[16 * 65];  // [j][d_local]
    const int tid = threadIdx.x;
    const int tx = tid & 15, ty = tid >> 4;
    const int k0 = blockIdx.y * 64;
    const int d0 = blockIdx.x * 64;
    const int rl = tid >> 2;         // 0..63
    const int j4 = (tid & 3) << 2;   // 0,4,8,12

    float acc[4][4];
#pragma unroll
    for (int u = 0; u < 4; u++)
#pragma unroll
        for (int v = 0; v < 4; v++) acc[u][v] = 0.f;

    for (int j0 = 0; j0 < DD; j0 += 16) {
        float4 va = *(const float4*)&emb[(k0 + rl) * DD + j0 + j4];
        float4 vb = *(const float4*)&pw[(d0 + rl) * DD + j0 + j4];
        As[(j4 + 0) * 65 + rl] = va.x;  As[(j4 + 1) * 65 + rl] = va.y;
        As[(j4 + 2) * 65 + rl] = va.z;  As[(j4 + 3) * 65 + rl] = va.w;
        Bs[(j4 + 0) * 65 + rl] = vb.x;  Bs[(j4 + 1) * 65 + rl] = vb.y;
        Bs[(j4 + 2) * 65 + rl] = vb.z;  Bs[(j4 + 3) * 65 + rl] = vb.w;
        __syncthreads();
#pragma unroll
        for (int jj = 0; jj < 16; jj++) {
            const float* ap = &As[jj * 65 + ty * 4];
            const float* bp = &Bs[jj * 65 + tx * 4];
            float a0 = ap[0], a1 = ap[1], a2 = ap[2], a3 = ap[3];
            float b0 = bp[0], b1 = bp[1], b2 = bp[2], b3 = bp[3];
            acc[0][0] = fmaf(a0, b0, acc[0][0]); acc[0][1] = fmaf(a0, b1, acc[0][1]);
            acc[0][2] = fmaf(a0, b2, acc[0][2]); acc[0][3] = fmaf(a0, b3, acc[0][3]);
            acc[1][0] = fmaf(a1, b0, acc[1][0]); acc[1][1] = fmaf(a1, b1, acc[1][1]);
            acc[1][2] = fmaf(a1, b2, acc[1][2]); acc[1][3] = fmaf(a1, b3, acc[1][3]);
            acc[2][0] = fmaf(a2, b0, acc[2][0]); acc[2][1] = fmaf(a2, b1, acc[2][1]);
            acc[2][2] = fmaf(a2, b2, acc[2][2]); acc[2][3] = fmaf(a2, b3, acc[2][3]);
            acc[3][0] = fmaf(a3, b0, acc[3][0]); acc[3][1] = fmaf(a3, b1, acc[3][1]);
            acc[3][2] = fmaf(a3, b2, acc[3][2]); acc[3][3] = fmaf(a3, b3, acc[3][3]);
        }
        __syncthreads();
    }
#pragma unroll
    for (int u = 0; u < 4; u++) {
        int k = k0 + ty * 4 + u;
        float4 w = make_float4(acc[u][0], acc[u][1], acc[u][2], acc[u][3]);
        *(float4*)&g_codebook[k * DD + d0 + tx * 4] = w;
    }
}

// ---------------------------------------------------------------------------
// Kernel 2: fused distance GEMM + quantized-score running argmin.
// Reference semantics (fp32 per-op rounding):
//   fl(zn + cn) == zn  (cn ~1.3e-6 < ulp(zn)/2 always), so
//   d_k = fl(zn - fl(2*dot_nk)); argmin with first-index tie-break.
// We reproduce exactly: s = fmaf(-2, acc, zn)  (x2 exact -> single rounding),
// with acc accumulated in-order d=0..255, single fp32 accumulator (matches
// cuBLAS SGEMM chain bit-for-bit). zn may be computed in any order: any fp32
// zn in the same binade shifts all d_k by an exact grid multiple, preserving
// ranking AND ties.
// ---------------------------------------------------------------------------
__global__ void argmin_kernel(const float* __restrict__ z,
                              float* __restrict__ idxf) {
    extern __shared__ float smem[];
    float* Zs   = smem;                 // 256*65 (z tile, [d][m])
    float* Es   = Zs + 256 * 65;        // 16*65  (code tile, [d][k])
    float* zns  = Es + 16 * 65;         // 64     (||z_row||^2)
    float* redv = zns + 64;             // 64*16
    int*   redi = (int*)(redv + 1024);  // 64*16

    const int tid = threadIdx.x;
    const int tx = tid & 15, ty = tid >> 4;
    const int n0 = blockIdx.x * 64;
    const int b = n0 >> 10;
    const int hw0 = n0 & 1023;
    const float* zb = z + b * CHW + hw0;

    // Load 64 z-rows, transposed to [d][m]
    for (int e = tid; e < 64 * DD; e += 256) {
        int d = e >> 6, m = e & 63;
        Zs[d * 65 + m] = zb[d * HW + m];
    }
    __syncthreads();

    // zn per row (sequential fp32; order-insensitive up to binade)
    if (tid < 64) {
        float s = 0.f;
#pragma unroll 8
        for (int d = 0; d < DD; d++) { float v = Zs[d * 65 + tid]; s = fmaf(v, v, s); }
        zns[tid] = s;
    }

    float minv0 = 3.4e38f, minv1 = 3.4e38f, minv2 = 3.4e38f, minv3 = 3.4e38f;
    int   mini0 = 0, mini1 = 0, mini2 = 0, mini3 = 0;

    const int rl  = tid >> 2;        // code row within 64-chunk
    const int j4  = (tid & 3) << 2;  // d sub-offset
    const int zb4 = ty * 4;          // my 4 z-rows
    const int eb4 = tx * 4;          // my 4 codes

    for (int k0 = 0; k0 < KC; k0 += 64) {
        float acc[4][4];
#pragma unroll
        for (int u = 0; u < 4; u++)
#pragma unroll
            for (int v = 0; v < 4; v++) acc[u][v] = 0.f;

        for (int d0 = 0; d0 < DD; d0 += 16) {
            float4 v = *(const float4*)&g_codebook[(k0 + rl) * DD + d0 + j4];
            Es[(j4 + 0) * 65 + rl] = v.x;  Es[(j4 + 1) * 65 + rl] = v.y;
            Es[(j4 + 2) * 65 + rl] = v.z;  Es[(j4 + 3) * 65 + rl] = v.w;
            __syncthreads();
#pragma unroll
            for (int dd = 0; dd < 16; dd++) {
                const float* zp = &Zs[(d0 + dd) * 65 + zb4];
                const float* ep = &Es[dd * 65 + eb4];
                float a0 = zp[0], a1 = zp[1], a2 = zp[2], a3 = zp[3];
                float b0 = ep[0], b1 = ep[1], b2 = ep[2], b3 = ep[3];
                acc[0][0] = fmaf(a0, b0, acc[0][0]); acc[0][1] = fmaf(a0, b1, acc[0][1]);
                acc[0][2] = fmaf(a0, b2, acc[0][2]); acc[0][3] = fmaf(a0, b3, acc[0][3]);
                acc[1][0] = fmaf(a1, b0, acc[1][0]); acc[1][1] = fmaf(a1, b1, acc[1][1]);
                acc[1][2] = fmaf(a1, b2, acc[1][2]); acc[1][3] = fmaf(a1, b3, acc[1][3]);
                acc[2][0] = fmaf(a2, b0, acc[2][0]); acc[2][1] = fmaf(a2, b1, acc[2][1]);
                acc[2][2] = fmaf(a2, b2, acc[2][2]); acc[2][3] = fmaf(a2, b3, acc[2][3]);
                acc[3][0] = fmaf(a3, b0, acc[3][0]); acc[3][1] = fmaf(a3, b1, acc[3][1]);
                acc[3][2] = fmaf(a3, b2, acc[3][2]); acc[3][3] = fmaf(a3, b3, acc[3][3]);
            }
            __syncthreads();
        }
        // epilogue: quantized score + running argmin (ascending k, strict <)
        float zn0 = zns[zb4 + 0], zn1 = zns[zb4 + 1];
        float zn2 = zns[zb4 + 2], zn3 = zns[zb4 + 3];
#pragma unroll
        for (int vv = 0; vv < 4; vv++) {
            int kk = k0 + eb4 + vv;
            float s0 = fmaf(-2.f, acc[0][vv], zn0);  // == fl(zn - fl(2*dot))
            float s1 = fmaf(-2.f, acc[1][vv], zn1);
            float s2 = fmaf(-2.f, acc[2][vv], zn2);
            float s3 = fmaf(-2.f, acc[3][vv], zn3);
            if (s0 < minv0) { minv0 = s0; mini0 = kk; }
            if (s1 < minv1) { minv1 = s1; mini1 = kk; }
            if (s2 < minv2) { minv2 = s2; mini2 = kk; }
            if (s3 < minv3) { minv3 = s3; mini3 = kk; }
        }
    }

    // cross-thread reduction: 16 candidates per row, lexicographic (val, idx)
    redv[(zb4 + 0) * 16 + tx] = minv0; redi[(zb4 + 0) * 16 + tx] = mini0;
    redv[(zb4 + 1) * 16 + tx] = minv1; redi[(zb4 + 1) * 16 + tx] = mini1;
    redv[(zb4 + 2) * 16 + tx] = minv2; redi[(zb4 + 2) * 16 + tx] = mini2;
    redv[(zb4 + 3) * 16 + tx] = minv3; redi[(zb4 + 3) * 16 + tx] = mini3;
    __syncthreads();
    if (tid < 64) {
        float bv = redv[tid * 16]; int bi = redi[tid * 16];
#pragma unroll
        for (int j = 1; j < 16; j++) {
            float v = redv[tid * 16 + j]; int i2 = redi[tid * 16 + j];
            if (v < bv || (v == bv && i2 < bi)) { bv = v; bi = i2; }
        }
        g_minidx[n0 + tid] = bi;
        if (idxf) idxf[n0 + tid] = (float)bi;
    }
}

// ---------------------------------------------------------------------------
// Kernel 3: gather codebook rows, write straight-through output transposed
// back to [B,C,H,W]; accumulate squared error.
// out = fl(zt + fl(zq - zt)) exactly as the reference FP ops (NOT just zq —
// differs by up to ~8.6e-4 relative).
// ---------------------------------------------------------------------------
__global__ void gather_out(const float* __restrict__ z, float* __restrict__ out) {
    __shared__ float s[256 * 33];
    const int tid = threadIdx.x;
    const int n0 = blockIdx.x * 32;
    const int b = n0 >> 10, hw0 = n0 & 1023;

#pragma unroll 1
    for (int nl = 0; nl < 32; nl++) {
        int ci = g_minidx[n0 + nl];
        s[tid * 33 + nl] = g_codebook[ci * DD + tid];
    }
    __syncthreads();

    float local = 0.f;
    const float* zb = z + b * CHW + hw0;
    float* ob = out + b * CHW + hw0;
    for (int e = tid; e < 32 * DD; e += 256) {
        int c = e >> 5, hl = e & 31;
        float q  = s[c * 33 + hl];
        float zv = zb[c * HW + hl];
        float d  = q - zv;
        ob[c * HW + hl] = zv + d;     // straight-through, two roundings
        local = fmaf(d, d, local);
    }
    __syncthreads();
    float* red = s;
    red[tid] = local;
    __syncthreads();
    for (int o = 128; o; o >>= 1) {
        if (tid < o) red[tid] += red[tid + o];
        __syncthreads();
    }
    if (tid == 0) g_partials[blockIdx.x] = red[0];
}

// ---------------------------------------------------------------------------
// Kernel 4: deterministic final reduction + loss scalars
// ---------------------------------------------------------------------------
__global__ void finalize_kernel(float* __restrict__ outp, int has_scalars) {
    __shared__ float red[512];
    const int tid = threadIdx.x;
    red[tid] = g_partials[tid];
    __syncthreads();
    for (int o = 256; o; o >>= 1) {
        if (tid < o) red[tid] += red[tid + o];
        __syncthreads();
    }
    if (tid == 0 && has_scalars) {
        float mse = red[0] * (1.0f / 4194304.0f);
        float cl  = 0.25f * mse;
        float bl  = mse;
        outp[4194304] = cl + bl;
        outp[4194305] = cl;
        outp[4194306] = bl;
    }
}

// ---------------------------------------------------------------------------
extern "C" void kernel_launch(void* const* d_in, const int* in_sizes, int n_in,
                              void* d_out, int out_size) {
    const float* z   = (const float*)d_in[0];   // [16,256,32,32]
    const float* emb = (const float*)d_in[1];   // [8192,256]
    const float* pw  = (const float*)d_in[2];   // [256,256]
    float* out = (float*)d_out;

    const int SMEM_ARG = (256 * 65 + 16 * 65 + 64 + 1024 + 1024) * 4;  // 79168 B
    cudaFuncSetAttribute(argmin_kernel,
                         cudaFuncAttributeMaxDynamicSharedMemorySize, SMEM_ARG);

    codebook_gemm<<<dim3(4, 128), 256>>>(emb, pw);

    // Output layout: out(4194304) | loss | commit | cb_loss | idx(16384)
    float* idxf = nullptr;
    if (out_size >= 4194307 + NR) idxf = out + 4194307;
    argmin_kernel<<<256, 256, SMEM_ARG>>>(z, idxf);

    gather_out<<<512, 256>>>(z, out);
    finalize_kernel<<<1, 512>>>(out, (out_size >= 4194307) ? 1 : 0);
}